// round 11
// baseline (speedup 1.0000x reference)
#include <cuda_runtime.h>
#include <math.h>

#define L 16
#define C 128
#define HH 96
#define WW 96
#define HW (HH*WW)          // 9216
#define CHW (C*HW)          // 1179648
#define KT 28               // 25 real taps + 3 zero pads (14/14 split)

typedef unsigned long long ull;

// ---------------- scratch (device globals; no runtime allocation) -------------
__device__ float2 g_weff2[C*KT];       // [c][k] folded conv weights, dup {w,w}; k>=25 zero
__device__ float  g_WvT[C*C];          // WvT[k][c] = Wv[c][k]
__device__ float  g_t[KT*L*HW];        // rank-25 projection [l][k][hw] (+3 dummy rows)
__device__ float  g_Ak[L*HW];          // pre-softmax scores [j][hw]
__device__ float  g_xbar[C*HW];        // softmax-weighted frame average [c][hw]

// ---------------- 1. fold Wk into the 25 per-tap projection vectors ----------
// weff[c][k] = sum_d Wa[C+d][k] * Wk[d][c]   (bk/ba/Wq/bq all cancel in softmax)
__global__ void fold_kernel(const float* __restrict__ Wk,
                            const float* __restrict__ Wa) {
    int k = blockIdx.x;      // 0..27
    int c = threadIdx.x;     // 0..127
    float acc = 0.f;
    if (k < 25) {
        #pragma unroll 4
        for (int d = 0; d < C; d++)
            acc += Wa[(C + d) * 25 + k] * Wk[d * C + c];
    }
    g_weff2[c * KT + k] = make_float2(acc, acc);
}

// ---------------- 2a/2b. transpose Wv (split to position proj at capture idx 3)
__global__ void transpose_wv_a(const float* __restrict__ Wv) {
    int k = blockIdx.x;                // 0..63
    int c = threadIdx.x;
    g_WvT[k * C + c] = Wv[c * C + k];
}
__global__ void transpose_wv_b(const float* __restrict__ Wv) {
    int k = 64 + blockIdx.x;           // 64..127
    int c = threadIdx.x;
    g_WvT[k * C + c] = Wv[c * C + k];
}

// ---------------- 3. t[l][k][hw] = sum_c weff[c][k] * x[l][c][hw] ------------
// 128-thread blocks; blockIdx.x = (hwblk<<1)|half; half picks taps [0,14)/[14,28).
// Thread owns 4 consecutive pixels (float4 load, two f32x2 acc banks). Weights
// via LDS.64 broadcast (1 wavefront each), each feeding TWO FFMA2 -> crossbar
// and FMA pipes balanced (~224 wavefronts == ~224 FFMA2-issue cyc per SM/ch).
// 576 blocks, 6 blocks/SM = 24 warps/SM (reg cap 85 via launch_bounds).
__global__ void __launch_bounds__(128, 6) proj_kernel(const float* __restrict__ x) {
    __shared__ ull ws2[C * 14];   // this half's weights (dup pairs), 14.3 KB
    const int tid   = threadIdx.x;           // 0..127
    const int l     = blockIdx.y;
    const int half  = blockIdx.x & 1;
    const int hwblk = blockIdx.x >> 1;       // 0..17
    const int p4    = hwblk * 512 + tid * 4; // pixel base
    const int k0    = half * 14;

    const ull* wsrc = (const ull*)g_weff2;
    #pragma unroll
    for (int i = tid; i < C * 14; i += 128) {
        int c  = i / 14;
        int kk = i - c * 14;
        ws2[i] = wsrc[c * KT + k0 + kk];
    }
    __syncthreads();

    ull acc0[14], acc1[14];
    #pragma unroll
    for (int k = 0; k < 14; k++) { acc0[k] = 0ull; acc1[k] = 0ull; }

    const float4* xl = (const float4*)(x + (size_t)l * CHW + p4);
    #pragma unroll 2
    for (int c = 0; c < C; c++) {
        float4 v = xl[c * (HW / 4)];
        ull a01, a23;
        asm("mov.b64 %0, {%1, %2};" : "=l"(a01) : "f"(v.x), "f"(v.y));
        asm("mov.b64 %0, {%1, %2};" : "=l"(a23) : "f"(v.z), "f"(v.w));
        const ull* wc = &ws2[c * 14];
        #pragma unroll
        for (int k = 0; k < 14; k++) {
            ull w = wc[k];   // one LDS.64 broadcast -> two FFMA2
            asm("fma.rn.f32x2 %0, %1, %2, %0;" : "+l"(acc0[k]) : "l"(w), "l"(a01));
            asm("fma.rn.f32x2 %0, %1, %2, %0;" : "+l"(acc1[k]) : "l"(w), "l"(a23));
        }
    }

    #pragma unroll
    for (int k = 0; k < 14; k++) {
        float f0, f1, f2, f3;
        asm("mov.b64 {%0, %1}, %2;" : "=f"(f0), "=f"(f1) : "l"(acc0[k]));
        asm("mov.b64 {%0, %1}, %2;" : "=f"(f2), "=f"(f3) : "l"(acc1[k]));
        // row k0+k; rows 25..27 are dummy sinks (zero weights), never read
        *(float4*)(g_t + ((size_t)l * KT + k0 + k) * HW + p4) = make_float4(f0, f1, f2, f3);
    }
}

// ---------------- 4. Ak[l][hw] = 25-tap shifted sum of t ---------------------
__global__ void ak_kernel() {
    const int l  = blockIdx.y;
    const int hw = blockIdx.x * 256 + threadIdx.x;
    const int h  = hw / WW;
    const int w  = hw - h * WW;

    const float* tl = g_t + (size_t)l * KT * HW;
    float acc = 0.f;
    #pragma unroll
    for (int kh = 0; kh < 5; kh++) {
        const int hh = h + kh - 2;
        const bool hok = (unsigned)hh < HH;
        #pragma unroll
        for (int kw = 0; kw < 5; kw++) {
            const int ww = w + kw - 2;
            if (hok && (unsigned)ww < WW)
                acc += tl[(kh * 5 + kw) * HW + hh * WW + ww];
        }
    }
    g_Ak[l * HW + hw] = acc;
}

// ---------------- 5. fused softmax + xbar ------------------------------------
// xbar[c][hw] = sum_j softmax_j(Ak)[j][hw] * x[j][c][hw]
// grid (9, 32), block 256; thread owns 4 consecutive pixels (float4) x 4 channels.
__global__ void xbarsm_kernel(const float* __restrict__ x) {
    const int p4    = blockIdx.x * 1024 + threadIdx.x * 4;   // pixel base
    const int cbase = blockIdx.y * 4;

    float4 a[L];
    #pragma unroll
    for (int j = 0; j < L; j++)
        a[j] = *(const float4*)&g_Ak[j * HW + p4];

    float4 mx = a[0];
    #pragma unroll
    for (int j = 1; j < L; j++) {
        mx.x = fmaxf(mx.x, a[j].x); mx.y = fmaxf(mx.y, a[j].y);
        mx.z = fmaxf(mx.z, a[j].z); mx.w = fmaxf(mx.w, a[j].w);
    }
    float4 s = make_float4(0.f, 0.f, 0.f, 0.f);
    #pragma unroll
    for (int j = 0; j < L; j++) {
        a[j].x = __expf(a[j].x - mx.x); s.x += a[j].x;
        a[j].y = __expf(a[j].y - mx.y); s.y += a[j].y;
        a[j].z = __expf(a[j].z - mx.z); s.z += a[j].z;
        a[j].w = __expf(a[j].w - mx.w); s.w += a[j].w;
    }
    const float4 inv = make_float4(1.f / s.x, 1.f / s.y, 1.f / s.z, 1.f / s.w);

    float4 acc[4];
    #pragma unroll
    for (int i = 0; i < 4; i++) acc[i] = make_float4(0.f, 0.f, 0.f, 0.f);

    #pragma unroll
    for (int j = 0; j < L; j++) {
        const float* xj = x + (size_t)(j * C + cbase) * HW + p4;
        #pragma unroll
        for (int i = 0; i < 4; i++) {
            const float4 xv = *(const float4*)&xj[i * HW];
            acc[i].x += a[j].x * xv.x;
            acc[i].y += a[j].y * xv.y;
            acc[i].z += a[j].z * xv.z;
            acc[i].w += a[j].w * xv.w;
        }
    }
    #pragma unroll
    for (int i = 0; i < 4; i++) {
        float4 r = make_float4(acc[i].x * inv.x, acc[i].y * inv.y,
                               acc[i].z * inv.z, acc[i].w * inv.w);
        *(float4*)&g_xbar[(cbase + i) * HW + p4] = r;
    }
}

// ---------------- 6. out[f][c][hw] = Wv . xbar + bv, broadcast to 16 frames --
__global__ void gemm_out_kernel(const float* __restrict__ bv,
                                float* __restrict__ out) {
    __shared__ float wv_s[16][64];
    __shared__ float xb_s[16][64];
    const int tid = threadIdx.y * 16 + threadIdx.x;
    const int pG = blockIdx.x * 64;
    const int cG = blockIdx.y * 64;

    const int sr   = tid >> 4;          // 0..15
    const int sc4  = (tid & 15) * 4;    // 0..60

    float acc[4][4];
    #pragma unroll
    for (int i = 0; i < 4; i++)
        #pragma unroll
        for (int j = 0; j < 4; j++) acc[i][j] = 0.f;

    for (int k0 = 0; k0 < C; k0 += 16) {
        *(float4*)&wv_s[sr][sc4] = *(const float4*)&g_WvT[(k0 + sr) * C + cG + sc4];
        *(float4*)&xb_s[sr][sc4] = *(const float4*)&g_xbar[(k0 + sr) * HW + pG + sc4];
        __syncthreads();
        #pragma unroll
        for (int kk = 0; kk < 16; kk++) {
            const float4 wv4 = *(const float4*)&wv_s[kk][threadIdx.y * 4];
            const float4 xb4 = *(const float4*)&xb_s[kk][threadIdx.x * 4];
            float wr[4] = {wv4.x, wv4.y, wv4.z, wv4.w};
            float xr[4] = {xb4.x, xb4.y, xb4.z, xb4.w};
            #pragma unroll
            for (int ci = 0; ci < 4; ci++)
                #pragma unroll
                for (int pi = 0; pi < 4; pi++)
                    acc[ci][pi] += wr[ci] * xr[pi];
        }
        __syncthreads();
    }

    const int c0 = cG + threadIdx.y * 4;
    const int p0 = pG + threadIdx.x * 4;
    #pragma unroll
    for (int ci = 0; ci < 4; ci++) {
        float b = bv[c0 + ci];
        float4 v = make_float4(acc[ci][0] + b, acc[ci][1] + b,
                               acc[ci][2] + b, acc[ci][3] + b);
        #pragma unroll
        for (int f = 0; f < L; f++)
            *(float4*)&out[(size_t)(f * C + c0 + ci) * HW + p0] = v;
    }
}

// ---------------- launch -----------------------------------------------------
extern "C" void kernel_launch(void* const* d_in, const int* in_sizes, int n_in,
                              void* d_out, int out_size) {
    const float* x  = (const float*)d_in[0];
    // d_in[1]=Wq, d_in[2]=bq unused (cancel in softmax over j)
    const float* Wk = (const float*)d_in[3];
    // d_in[4]=bk unused (border bias map is j-independent -> cancels)
    const float* Wv = (const float*)d_in[5];
    const float* bv = (const float*)d_in[6];
    const float* Wa = (const float*)d_in[7];
    // d_in[8]=ba unused (cancels)
    float* out = (float*)d_out;

    // order chosen so the single ncu capture (launch index 3) profiles proj
    fold_kernel<<<KT, 128>>>(Wk, Wa);                     // 0
    transpose_wv_a<<<64, 128>>>(Wv);                      // 1
    transpose_wv_b<<<64, 128>>>(Wv);                      // 2
    proj_kernel<<<dim3(36, L), 128>>>(x);                 // 3  <- profiled (576 blocks)
    ak_kernel<<<dim3(36, L), 256>>>();                    // 4
    xbarsm_kernel<<<dim3(9, 32), 256>>>(x);               // 5
    gemm_out_kernel<<<dim3(HW / 64, 2), dim3(16, 16)>>>(bv, out);  // 6
}

// round 12
// speedup vs baseline: 1.1569x; 1.1569x over previous
#include <cuda_runtime.h>
#include <math.h>

#define L 16
#define C 128
#define HH 96
#define WW 96
#define HW (HH*WW)          // 9216
#define CHW (C*HW)          // 1179648

#define CG 16               // channels per group (pass A)
#define NPART (C/CG)        // 8
#define RPB 16              // rows per block
#define TPB 192             // 16 rows x 12 strips of 8 px

typedef unsigned long long ull;

// ---------------- scratch (device globals; no runtime allocation) -------------
__device__ float2 g_weff2[C*25];          // [c][k] folded conv weights, dup {w,w}
__device__ float  g_WvT[C*C];             // WvT[k][c] = Wv[c][k]
__device__ float  g_u[NPART*L*5*HW];      // partial horiz conv [part][l][kh][hw] 23.6MB
__device__ float  g_Ak[L*HW];             // pre-softmax scores [j][hw]
__device__ float  g_xbar[C*HW];           // softmax-weighted frame average [c][hw]

// ---------------- 1. fold Wk into the 25 per-tap projection vectors ----------
// weff[c][k] = sum_d Wa[C+d][k] * Wk[d][c]   (bk/ba/Wq/bq all cancel in softmax)
__global__ void fold_kernel(const float* __restrict__ Wk,
                            const float* __restrict__ Wa) {
    int k = blockIdx.x;      // 0..24
    int c = threadIdx.x;     // 0..127
    float acc = 0.f;
    #pragma unroll 4
    for (int d = 0; d < C; d++)
        acc += Wa[(C + d) * 25 + k] * Wk[d * C + c];
    g_weff2[c * 25 + k] = make_float2(acc, acc);
}

// ---------------- 2a/2b. transpose Wv (split to position convh at capture idx 3)
__global__ void transpose_wv_a(const float* __restrict__ Wv) {
    int k = blockIdx.x;                // 0..63
    int c = threadIdx.x;
    g_WvT[k * C + c] = Wv[c * C + k];
}
__global__ void transpose_wv_b(const float* __restrict__ Wv) {
    int k = 64 + blockIdx.x;           // 64..127
    int c = threadIdx.x;
    g_WvT[k * C + c] = Wv[c * C + k];
}

// ---------------- 3. Pass A: fused projection + HORIZONTAL 5-tap conv --------
// u[part][l][kh][h][w] = sum_{c in part} sum_kw weff[c][kh*5+kw] * x[l][c][h][w+kw-2]
// Thread: one row-strip of 8 px. Accumulators: 5 kh x 4 f32x2 = 40 regs.
// Per channel: 6 LDG.64 (12 px incl w-halo) + 25 LDS.64 (weights, each feeds
// 4 FFMA2) + 100 FFMA2  ->  FMA-pipe bound; LDS at half the FMA time.
// Grid 6 rowblk x 8 cgroup x 16 frames = 768 blocks of 192 thr.
__global__ void __launch_bounds__(TPB, 4) convh_kernel(const float* __restrict__ x) {
    __shared__ ull ws2[CG * 25];   // this group's duplicated weights, 3.2 KB
    const int tid    = threadIdx.x;
    const int rowblk = blockIdx.x;      // 0..5
    const int part   = blockIdx.y;      // 0..7
    const int l      = blockIdx.z;      // 0..15
    const int row    = tid / 12;        // 0..15
    const int strip  = tid - row * 12;  // 0..11
    const int w0     = strip * 8;
    const int h      = rowblk * RPB + row;
    const int c0     = part * CG;

    const ull* wsrc = (const ull*)g_weff2;
    #pragma unroll
    for (int i = tid; i < CG * 25; i += TPB) {
        int c = i / 25, k = i - c * 25;
        ws2[i] = wsrc[(c0 + c) * 25 + k];
    }
    __syncthreads();

    ull acc[5][4];
    #pragma unroll
    for (int kh = 0; kh < 5; kh++)
        #pragma unroll
        for (int j = 0; j < 4; j++) acc[kh][j] = 0ull;

    const bool led = (strip == 0);
    const bool red = (strip == 11);
    const float* xb = x + (size_t)l * CHW + (size_t)c0 * HW + h * WW + (w0 - 2);

    #pragma unroll 2
    for (int c = 0; c < CG; c++) {
        const float* xr = xb + c * HW;
        float2 f0 = led ? make_float2(0.f, 0.f) : *(const float2*)(xr);
        float2 f1 = *(const float2*)(xr + 2);
        float2 f2 = *(const float2*)(xr + 4);
        float2 f3 = *(const float2*)(xr + 6);
        float2 f4 = *(const float2*)(xr + 8);
        float2 f5 = red ? make_float2(0.f, 0.f) : *(const float2*)(xr + 10);

        ull a[6], m[5];
        asm("mov.b64 %0, {%1, %2};" : "=l"(a[0]) : "f"(f0.x), "f"(f0.y));
        asm("mov.b64 %0, {%1, %2};" : "=l"(a[1]) : "f"(f1.x), "f"(f1.y));
        asm("mov.b64 %0, {%1, %2};" : "=l"(a[2]) : "f"(f2.x), "f"(f2.y));
        asm("mov.b64 %0, {%1, %2};" : "=l"(a[3]) : "f"(f3.x), "f"(f3.y));
        asm("mov.b64 %0, {%1, %2};" : "=l"(a[4]) : "f"(f4.x), "f"(f4.y));
        asm("mov.b64 %0, {%1, %2};" : "=l"(a[5]) : "f"(f5.x), "f"(f5.y));
        asm("mov.b64 %0, {%1, %2};" : "=l"(m[0]) : "f"(f0.y), "f"(f1.x));
        asm("mov.b64 %0, {%1, %2};" : "=l"(m[1]) : "f"(f1.y), "f"(f2.x));
        asm("mov.b64 %0, {%1, %2};" : "=l"(m[2]) : "f"(f2.y), "f"(f3.x));
        asm("mov.b64 %0, {%1, %2};" : "=l"(m[3]) : "f"(f3.y), "f"(f4.x));
        asm("mov.b64 %0, {%1, %2};" : "=l"(m[4]) : "f"(f4.y), "f"(f5.x));

        const ull* wc = &ws2[c * 25];
        #pragma unroll
        for (int kh = 0; kh < 5; kh++) {
            ull w0v = wc[kh * 5 + 0];
            ull w1v = wc[kh * 5 + 1];
            ull w2v = wc[kh * 5 + 2];
            ull w3v = wc[kh * 5 + 3];
            ull w4v = wc[kh * 5 + 4];
            #pragma unroll
            for (int j = 0; j < 4; j++) {
                asm("fma.rn.f32x2 %0, %1, %2, %0;" : "+l"(acc[kh][j]) : "l"(w0v), "l"(a[j]));
                asm("fma.rn.f32x2 %0, %1, %2, %0;" : "+l"(acc[kh][j]) : "l"(w1v), "l"(m[j]));
                asm("fma.rn.f32x2 %0, %1, %2, %0;" : "+l"(acc[kh][j]) : "l"(w2v), "l"(a[j + 1]));
                asm("fma.rn.f32x2 %0, %1, %2, %0;" : "+l"(acc[kh][j]) : "l"(w3v), "l"(m[j + 1]));
                asm("fma.rn.f32x2 %0, %1, %2, %0;" : "+l"(acc[kh][j]) : "l"(w4v), "l"(a[j + 2]));
            }
        }
    }

    float* ub = g_u + (((size_t)part * L + l) * 5) * HW + h * WW + w0;
    #pragma unroll
    for (int kh = 0; kh < 5; kh++) {
        #pragma unroll
        for (int j = 0; j < 4; j++) {
            float lo, hi;
            asm("mov.b64 {%0, %1}, %2;" : "=f"(lo), "=f"(hi) : "l"(acc[kh][j]));
            *(float2*)(ub + kh * HW + 2 * j) = make_float2(lo, hi);
        }
    }
}

// ---------------- 4. Pass B: vertical 5-tap + partial-sum -> Ak --------------
// Ak[l][hw] = sum_part sum_kh u[part][l][kh][h+kh-2][w].  u is L2-resident.
__global__ void akb_kernel() {
    const int l  = blockIdx.y;
    const int p4 = (blockIdx.x * 256 + threadIdx.x) * 4;
    const int h  = p4 / WW;
    const int w  = p4 - h * WW;

    float4 acc = make_float4(0.f, 0.f, 0.f, 0.f);
    #pragma unroll
    for (int kh = 0; kh < 5; kh++) {
        const int hh = h + kh - 2;
        if ((unsigned)hh >= HH) continue;
        #pragma unroll
        for (int part = 0; part < NPART; part++) {
            const float4 v = *(const float4*)&g_u[
                (((size_t)part * L + l) * 5 + kh) * HW + hh * WW + w];
            acc.x += v.x; acc.y += v.y; acc.z += v.z; acc.w += v.w;
        }
    }
    *(float4*)&g_Ak[l * HW + p4] = acc;
}

// ---------------- 5. fused softmax + xbar ------------------------------------
// xbar[c][hw] = sum_j softmax_j(Ak)[j][hw] * x[j][c][hw]
__global__ void xbarsm_kernel(const float* __restrict__ x) {
    const int p4    = blockIdx.x * 1024 + threadIdx.x * 4;   // pixel base
    const int cbase = blockIdx.y * 4;

    float4 a[L];
    #pragma unroll
    for (int j = 0; j < L; j++)
        a[j] = *(const float4*)&g_Ak[j * HW + p4];

    float4 mx = a[0];
    #pragma unroll
    for (int j = 1; j < L; j++) {
        mx.x = fmaxf(mx.x, a[j].x); mx.y = fmaxf(mx.y, a[j].y);
        mx.z = fmaxf(mx.z, a[j].z); mx.w = fmaxf(mx.w, a[j].w);
    }
    float4 s = make_float4(0.f, 0.f, 0.f, 0.f);
    #pragma unroll
    for (int j = 0; j < L; j++) {
        a[j].x = __expf(a[j].x - mx.x); s.x += a[j].x;
        a[j].y = __expf(a[j].y - mx.y); s.y += a[j].y;
        a[j].z = __expf(a[j].z - mx.z); s.z += a[j].z;
        a[j].w = __expf(a[j].w - mx.w); s.w += a[j].w;
    }
    const float4 inv = make_float4(1.f / s.x, 1.f / s.y, 1.f / s.z, 1.f / s.w);

    float4 acc[4];
    #pragma unroll
    for (int i = 0; i < 4; i++) acc[i] = make_float4(0.f, 0.f, 0.f, 0.f);

    #pragma unroll
    for (int j = 0; j < L; j++) {
        const float* xj = x + (size_t)(j * C + cbase) * HW + p4;
        #pragma unroll
        for (int i = 0; i < 4; i++) {
            const float4 xv = *(const float4*)&xj[i * HW];
            acc[i].x += a[j].x * xv.x;
            acc[i].y += a[j].y * xv.y;
            acc[i].z += a[j].z * xv.z;
            acc[i].w += a[j].w * xv.w;
        }
    }
    #pragma unroll
    for (int i = 0; i < 4; i++) {
        float4 r = make_float4(acc[i].x * inv.x, acc[i].y * inv.y,
                               acc[i].z * inv.z, acc[i].w * inv.w);
        *(float4*)&g_xbar[(cbase + i) * HW + p4] = r;
    }
}

// ---------------- 6. out[f][c][hw] = Wv . xbar + bv, broadcast to 16 frames --
__global__ void gemm_out_kernel(const float* __restrict__ bv,
                                float* __restrict__ out) {
    __shared__ float wv_s[16][64];
    __shared__ float xb_s[16][64];
    const int tid = threadIdx.y * 16 + threadIdx.x;
    const int pG = blockIdx.x * 64;
    const int cG = blockIdx.y * 64;

    const int sr   = tid >> 4;          // 0..15
    const int sc4  = (tid & 15) * 4;    // 0..60

    float acc[4][4];
    #pragma unroll
    for (int i = 0; i < 4; i++)
        #pragma unroll
        for (int j = 0; j < 4; j++) acc[i][j] = 0.f;

    for (int k0 = 0; k0 < C; k0 += 16) {
        *(float4*)&wv_s[sr][sc4] = *(const float4*)&g_WvT[(k0 + sr) * C + cG + sc4];
        *(float4*)&xb_s[sr][sc4] = *(const float4*)&g_xbar[(k0 + sr) * HW + pG + sc4];
        __syncthreads();
        #pragma unroll
        for (int kk = 0; kk < 16; kk++) {
            const float4 wv4 = *(const float4*)&wv_s[kk][threadIdx.y * 4];
            const float4 xb4 = *(const float4*)&xb_s[kk][threadIdx.x * 4];
            float wr[4] = {wv4.x, wv4.y, wv4.z, wv4.w};
            float xr[4] = {xb4.x, xb4.y, xb4.z, xb4.w};
            #pragma unroll
            for (int ci = 0; ci < 4; ci++)
                #pragma unroll
                for (int pi = 0; pi < 4; pi++)
                    acc[ci][pi] += wr[ci] * xr[pi];
        }
        __syncthreads();
    }

    const int c0 = cG + threadIdx.y * 4;
    const int p0 = pG + threadIdx.x * 4;
    #pragma unroll
    for (int ci = 0; ci < 4; ci++) {
        float b = bv[c0 + ci];
        float4 v = make_float4(acc[ci][0] + b, acc[ci][1] + b,
                               acc[ci][2] + b, acc[ci][3] + b);
        #pragma unroll
        for (int f = 0; f < L; f++)
            *(float4*)&out[(size_t)(f * C + c0 + ci) * HW + p0] = v;
    }
}

// ---------------- launch -----------------------------------------------------
extern "C" void kernel_launch(void* const* d_in, const int* in_sizes, int n_in,
                              void* d_out, int out_size) {
    const float* x  = (const float*)d_in[0];
    // d_in[1]=Wq, d_in[2]=bq unused (cancel in softmax over j)
    const float* Wk = (const float*)d_in[3];
    // d_in[4]=bk unused (border bias map is j-independent -> cancels)
    const float* Wv = (const float*)d_in[5];
    const float* bv = (const float*)d_in[6];
    const float* Wa = (const float*)d_in[7];
    // d_in[8]=ba unused (cancels)
    float* out = (float*)d_out;

    // order chosen so the single ncu capture (launch index 3) profiles convh
    fold_kernel<<<25, 128>>>(Wk, Wa);                         // 0
    transpose_wv_a<<<64, 128>>>(Wv);                          // 1
    transpose_wv_b<<<64, 128>>>(Wv);                          // 2
    convh_kernel<<<dim3(HH / RPB, NPART, L), TPB>>>(x);       // 3  <- profiled (768 blocks)
    akb_kernel<<<dim3(9, L), 256>>>();                        // 4
    xbarsm_kernel<<<dim3(9, 32), 256>>>(x);                   // 5
    gemm_out_kernel<<<dim3(HW / 64, 2), dim3(16, 16)>>>(bv, out);  // 6
}